// round 1
// baseline (speedup 1.0000x reference)
#include <cuda_runtime.h>

#define BROWS 2048
#define NCOL 8192
#define NV4 (NCOL/4)
#define BDIM 512
#define NWARP (BDIM/32)

// scratch for per-row loss partial sums (no allocations allowed)
__device__ float g_rowsum[BROWS];

__device__ __forceinline__ float warpRedSum(float v) {
#pragma unroll
    for (int o = 16; o > 0; o >>= 1) v += __shfl_xor_sync(0xffffffffu, v, o);
    return v;
}
__device__ __forceinline__ float warpRedMax(float v) {
#pragma unroll
    for (int o = 16; o > 0; o >>= 1) v = fmaxf(v, __shfl_xor_sync(0xffffffffu, v, o));
    return v;
}

__global__ __launch_bounds__(BDIM, 1)
void custom_loss_kernel(const float* __restrict__ yp,
                        const float* __restrict__ yt,
                        const float* __restrict__ Lam,
                        float* __restrict__ out /* out[0]=loss, out[1..]=Lambda */)
{
    __shared__ float r_sm[NCOL];
    __shared__ float part1[NWARP];
    __shared__ float part2[NWARP];

    const int row  = blockIdx.x;
    const int tid  = threadIdx.x;
    const int lane = tid & 31;
    const int wid  = tid >> 5;

    const float4* yp4 = (const float4*)yp + (size_t)row * NV4;
    const float4* yt4 = (const float4*)yt + (size_t)row * NV4;
    float4* rsm4 = (float4*)r_sm;

    // ---- pass 0: residuals into SMEM + row max ----
    float rmax = 0.f;
#pragma unroll 4
    for (int i = tid; i < NV4; i += BDIM) {
        float4 a = yp4[i], b = yt4[i];
        float4 r;
        r.x = fabsf(b.x - a.x); r.y = fabsf(b.y - a.y);
        r.z = fabsf(b.z - a.z); r.w = fabsf(b.w - a.w);
        rsm4[i] = r;
        rmax = fmaxf(rmax, fmaxf(fmaxf(r.x, r.y), fmaxf(r.z, r.w)));
    }
    rmax = warpRedMax(rmax);
    if (lane == 0) part1[wid] = rmax;
    __syncthreads();
    float m = part1[0];
#pragma unroll
    for (int w = 1; w < NWARP; w++) m = fmaxf(m, part1[w]);
    rmax = m;
    __syncthreads();

    // eps init: r_max / (log(2N) + 1e-8)
    const float LOGC = (float)(9.704060527839234 + 1e-8); // log(2*8192)
    float eps = fmaxf(rmax, 1e-8f) / LOGC;

    const float INVN = 1.0f / (float)NCOL;

    // ---- Newton iterations (all threads compute identical eps) ----
#pragma unroll 1
    for (int it = 0; it < 20; it++) {
        float eps_safe = fmaxf(eps, 1e-8f);
        float binv = 1.0f / eps_safe;
        float s1 = 0.f, s2 = 0.f;
#pragma unroll 4
        for (int i = tid; i < NCOL; i += BDIM) {
            float r = r_sm[i];
            float u = r * binv;
            float e  = __expf(u);
            float ei = __expf(-u);
            s1 += (e - ei);              // 2*sinh(u)
            s2 = fmaf(e + ei, u, s2);    // 2*cosh(u)*u
        }
        s1 = warpRedSum(s1);
        s2 = warpRedSum(s2);
        if (lane == 0) { part1[wid] = s1; part2[wid] = s2; }
        __syncthreads();
        float S1 = 0.f, S2 = 0.f;
#pragma unroll
        for (int w = 0; w < NWARP; w++) { S1 += part1[w]; S2 += part2[w]; }
        __syncthreads();
        float val  = 0.5f * S1 * INVN - 1.0f;
        float grad = -(0.5f * S2 * INVN) * binv;
        eps = eps - val / (grad - 1e-8f);
    }
    eps = fmaxf(eps, 1e-8f);
    float beta = 1.0f / (eps + 1e-6f);

    // ---- pass A: q_max ----
    float qmax = 0.f;
#pragma unroll 4
    for (int i = tid; i < NCOL; i += BDIM) {
        float u = r_sm[i] * beta;
        float q = 0.5f * (__expf(u) - __expf(-u));
        qmax = fmaxf(qmax, q);
    }
    qmax = warpRedMax(qmax);
    if (lane == 0) part1[wid] = qmax;
    __syncthreads();
    float qm = part1[0];
#pragma unroll
    for (int w = 1; w < NWARP; w++) qm = fmaxf(qm, part1[w]);
    __syncthreads();
    float qinv = 1.0f / (qm + 1e-20f);

    // ---- pass B: Lambda update + loss partial ----
    const float4* L4 = (const float4*)Lam + (size_t)row * NV4;
    float* outL = out + 1 + (size_t)row * NCOL;
    float ls = 0.f;
#pragma unroll 2
    for (int i = tid; i < NV4; i += BDIM) {
        float4 rr = rsm4[i];
        float4 lv = L4[i];
        float vo[4];
        float rv[4] = {rr.x, rr.y, rr.z, rr.w};
        float lm[4] = {lv.x, lv.y, lv.z, lv.w};
#pragma unroll
        for (int c = 0; c < 4; c++) {
            float u = rv[c] * beta;
            float q = 0.5f * (__expf(u) - __expf(-u));
            float lam_it = fmaf(0.9f, q * qinv, 0.1f);          // PHI*q_norm + (1-PHI)
            float upd = fmaf(0.99f, lm[c], 0.1f * lam_it);      // GAMMA*Lambda + ETA*lam_it
            vo[c] = upd;
            float p = upd * rv[c];
            ls = fmaf(p, p, ls);
        }
        // out+1 region is 4-byte aligned only -> scalar stores
        int base = i * 4;
        outL[base + 0] = vo[0];
        outL[base + 1] = vo[1];
        outL[base + 2] = vo[2];
        outL[base + 3] = vo[3];
    }
    ls = warpRedSum(ls);
    if (lane == 0) part2[wid] = ls;
    __syncthreads();
    if (tid == 0) {
        float s = 0.f;
#pragma unroll
        for (int w = 0; w < NWARP; w++) s += part2[w];
        g_rowsum[row] = s;
    }
}

__global__ void finalize_kernel(float* __restrict__ out)
{
    __shared__ float p[8];
    int tid = threadIdx.x;
    float s = 0.f;
    for (int i = tid; i < BROWS; i += 256) s += g_rowsum[i];
    s = warpRedSum(s);
    if ((tid & 31) == 0) p[tid >> 5] = s;
    __syncthreads();
    if (tid == 0) {
        float t = 0.f;
#pragma unroll
        for (int w = 0; w < 8; w++) t += p[w];
        out[0] = t * (1.0f / ((float)BROWS * (float)NCOL));
    }
}

extern "C" void kernel_launch(void* const* d_in, const int* in_sizes, int n_in,
                              void* d_out, int out_size)
{
    const float* yp  = (const float*)d_in[0];
    const float* yt  = (const float*)d_in[1];
    const float* Lam = (const float*)d_in[2];
    float* out = (float*)d_out;

    custom_loss_kernel<<<BROWS, BDIM>>>(yp, yt, Lam, out);
    finalize_kernel<<<1, 256>>>(out);
}

// round 4
// speedup vs baseline: 1.9005x; 1.9005x over previous
#include <cuda_runtime.h>

#define BROWS 2048
#define NCOL 8192
#define NV4 (NCOL/4)
#define BDIM 512
#define NWARP (BDIM/32)
#define EPT 16            // elements per thread
#define V4PT 4            // float4 loads per thread

__device__ float g_rowsum[BROWS];

__device__ __forceinline__ float warpRedSum(float v) {
#pragma unroll
    for (int o = 16; o > 0; o >>= 1) v += __shfl_xor_sync(0xffffffffu, v, o);
    return v;
}
__device__ __forceinline__ float warpRedMax(float v) {
#pragma unroll
    for (int o = 16; o > 0; o >>= 1) v = fmaxf(v, __shfl_xor_sync(0xffffffffu, v, o));
    return v;
}
__device__ __forceinline__ float ex2(float x) {
    float y;
    asm("ex2.approx.f32 %0, %1;" : "=f"(y) : "f"(x));
    return y;
}

__global__ __launch_bounds__(BDIM)
void custom_loss_kernel(const float* __restrict__ yp,
                        const float* __restrict__ yt,
                        const float* __restrict__ Lam,
                        float* __restrict__ out /* out[0]=loss, out[1..]=Lambda */)
{
    __shared__ float4 lam_sm[NV4];          // 32 KB Lambda prefetch
    __shared__ float pA[2][NWARP];          // double-buffered reduction scratch
    __shared__ float pB[2][NWARP];

    const int row  = blockIdx.x;
    const int tid  = threadIdx.x;
    const int lane = tid & 31;
    const int wid  = tid >> 5;

    const float4* yp4 = (const float4*)yp + (size_t)row * NV4;
    const float4* yt4 = (const float4*)yt + (size_t)row * NV4;
    const float4* L4  = (const float4*)Lam + (size_t)row * NV4;

    // ---- pass 0: residuals into registers + Lambda prefetch + row max ----
    float r[EPT];
    float rmax = 0.f;
#pragma unroll
    for (int k = 0; k < V4PT; k++) {
        int i = tid + k * BDIM;
        float4 a = yp4[i], b = yt4[i];
        lam_sm[i] = L4[i];                  // overlap Lambda DRAM read with Newton
        float rx = fabsf(b.x - a.x), ry = fabsf(b.y - a.y);
        float rz = fabsf(b.z - a.z), rw = fabsf(b.w - a.w);
        r[4*k+0] = rx; r[4*k+1] = ry; r[4*k+2] = rz; r[4*k+3] = rw;
        rmax = fmaxf(rmax, fmaxf(fmaxf(rx, ry), fmaxf(rz, rw)));
    }
    rmax = warpRedMax(rmax);
    if (lane == 0) pA[0][wid] = rmax;
    __syncthreads();
    float m = pA[0][0];
#pragma unroll
    for (int w = 1; w < NWARP; w++) m = fmaxf(m, pA[0][w]);
    rmax = m;
    // no barrier needed: next write to pA is to buffer parity 1

    const float LOGC  = (float)(9.704060527839234 + 1e-8);   // log(2*8192)
    const float LOG2E = 1.4426950408889634f;
    const float INVN  = 1.0f / (float)NCOL;

    float eps = fmaxf(rmax, 1e-8f) / LOGC;

    // ---- Newton with early exit (eps identical in all threads -> uniform) ----
    for (int it = 0; it < 20; it++) {
        int pb = (it + 1) & 1;              // iter 0 uses buffer 1 (buffer 0 busy above)
        float eps_safe = fmaxf(eps, 1e-8f);
        float binv = __fdividef(1.0f, eps_safe);
        float s1 = 0.f, s2 = 0.f;
#pragma unroll
        for (int j = 0; j < EPT; j++) {
            float u = r[j] * binv;
            float a = u * LOG2E;
            float e  = ex2(a);
            float ei = ex2(-a);
            s1 += (e - ei);                 // 2*sinh(u)
            s2 = fmaf(e + ei, u, s2);       // 2*cosh(u)*u
        }
        s1 = warpRedSum(s1);
        s2 = warpRedSum(s2);
        if (lane == 0) { pA[pb][wid] = s1; pB[pb][wid] = s2; }
        __syncthreads();
        float S1 = 0.f, S2 = 0.f;
#pragma unroll
        for (int w = 0; w < NWARP; w++) { S1 += pA[pb][w]; S2 += pB[pb][w]; }
        float val  = 0.5f * S1 * INVN - 1.0f;
        float grad = -(0.5f * S2 * INVN) * binv;
        eps = eps - val / (grad - 1e-8f);
        if (fabsf(val) < 1e-6f) break;      // converged; further iters sub-roundoff
    }
    eps = fmaxf(eps, 1e-8f);
    float beta = __fdividef(1.0f, eps + 1e-6f);

    // ---- q_max analytically: sinh monotone -> max at rmax ----
    float am = rmax * beta * LOG2E;
    float qmax = 0.5f * (ex2(am) - ex2(-am));
    float qinv = __fdividef(1.0f, qmax + 1e-20f);

    // ---- output pass: Lambda update + loss partial ----
    float* outL = out + 1 + (size_t)row * NCOL;
    float ls = 0.f;
#pragma unroll
    for (int k = 0; k < V4PT; k++) {
        int i = tid + k * BDIM;
        float4 lv = lam_sm[i];
        float lm[4] = {lv.x, lv.y, lv.z, lv.w};
        float vo[4];
#pragma unroll
        for (int c = 0; c < 4; c++) {
            float rv = r[4*k + c];
            float a = rv * beta * LOG2E;
            float q = 0.5f * (ex2(a) - ex2(-a));
            float lam_it = fmaf(0.9f, q * qinv, 0.1f);       // PHI*q_norm + (1-PHI)
            float upd = fmaf(0.99f, lm[c], 0.1f * lam_it);   // GAMMA*Lambda + ETA*lam_it
            vo[c] = upd;
            float p = upd * rv;
            ls = fmaf(p, p, ls);
        }
        int base = i * 4;                   // out+1 region is only 4B aligned
        outL[base + 0] = vo[0];
        outL[base + 1] = vo[1];
        outL[base + 2] = vo[2];
        outL[base + 3] = vo[3];
    }
    ls = warpRedSum(ls);
    if (lane == 0) pB[0][wid] = ls;
    __syncthreads();
    if (tid == 0) {
        float s = 0.f;
#pragma unroll
        for (int w = 0; w < NWARP; w++) s += pB[0][w];
        g_rowsum[row] = s;
    }
}

__global__ void finalize_kernel(float* __restrict__ out)
{
    __shared__ float p[8];
    int tid = threadIdx.x;
    float s = 0.f;
    for (int i = tid; i < BROWS; i += 256) s += g_rowsum[i];
    s = warpRedSum(s);
    if ((tid & 31) == 0) p[tid >> 5] = s;
    __syncthreads();
    if (tid == 0) {
        float t = 0.f;
#pragma unroll
        for (int w = 0; w < 8; w++) t += p[w];
        out[0] = t * (1.0f / ((float)BROWS * (float)NCOL));
    }
}

extern "C" void kernel_launch(void* const* d_in, const int* in_sizes, int n_in,
                              void* d_out, int out_size)
{
    const float* yp  = (const float*)d_in[0];
    const float* yt  = (const float*)d_in[1];
    const float* Lam = (const float*)d_in[2];
    float* out = (float*)d_out;

    custom_loss_kernel<<<BROWS, BDIM>>>(yp, yt, Lam, out);
    finalize_kernel<<<1, 256>>>(out);
}

// round 7
// speedup vs baseline: 2.1367x; 1.1243x over previous
#include <cuda_runtime.h>

#define BROWS 2048
#define NCOL 8192
#define NV4 (NCOL/4)
#define BDIM 512
#define NWARP (BDIM/32)
#define EPT 16            // elements per thread
#define V4PT 4            // float4 loads per thread

__device__ float g_rowsum[BROWS];
__device__ unsigned int g_count = 0;   // last-block counter; reset by last block

__device__ __forceinline__ float warpRedSum(float v) {
#pragma unroll
    for (int o = 16; o > 0; o >>= 1) v += __shfl_xor_sync(0xffffffffu, v, o);
    return v;
}
__device__ __forceinline__ float warpRedMax(float v) {
#pragma unroll
    for (int o = 16; o > 0; o >>= 1) v = fmaxf(v, __shfl_xor_sync(0xffffffffu, v, o));
    return v;
}
__device__ __forceinline__ float ex2(float x) {
    float y;
    asm("ex2.approx.f32 %0, %1;" : "=f"(y) : "f"(x));
    return y;
}

__global__ __launch_bounds__(BDIM)
void custom_loss_kernel(const float* __restrict__ yp,
                        const float* __restrict__ yt,
                        const float* __restrict__ Lam,
                        float* __restrict__ out /* out[0]=loss, out[1..]=Lambda */)
{
    __shared__ float4 lam_sm[NV4];          // 32 KB Lambda prefetch
    __shared__ float pA[2][NWARP];          // double-buffered reduction scratch
    __shared__ float pB[2][NWARP];
    __shared__ unsigned int isLast;

    const int row  = blockIdx.x;
    const int tid  = threadIdx.x;
    const int lane = tid & 31;
    const int wid  = tid >> 5;

    const float4* yp4 = (const float4*)yp + (size_t)row * NV4;
    const float4* yt4 = (const float4*)yt + (size_t)row * NV4;
    const float4* L4  = (const float4*)Lam + (size_t)row * NV4;

    // ---- pass 0: residuals into registers + Lambda prefetch + row max ----
    float r[EPT];
    float rmax = 0.f;
#pragma unroll
    for (int k = 0; k < V4PT; k++) {
        int i = tid + k * BDIM;
        float4 a = yp4[i], b = yt4[i];
        lam_sm[i] = L4[i];                  // overlap Lambda DRAM read with Newton
        float rx = fabsf(b.x - a.x), ry = fabsf(b.y - a.y);
        float rz = fabsf(b.z - a.z), rw = fabsf(b.w - a.w);
        r[4*k+0] = rx; r[4*k+1] = ry; r[4*k+2] = rz; r[4*k+3] = rw;
        rmax = fmaxf(rmax, fmaxf(fmaxf(rx, ry), fmaxf(rz, rw)));
    }
    rmax = warpRedMax(rmax);
    if (lane == 0) pA[0][wid] = rmax;
    __syncthreads();
    float m = pA[0][0];
#pragma unroll
    for (int w = 1; w < NWARP; w++) m = fmaxf(m, pA[0][w]);
    rmax = m;
    // no barrier needed: next write to pA is to buffer parity 1

    const float LOGC   = (float)(9.704060527839234 + 1e-8);  // log(2*8192)
    const float LOG2E  = 1.4426950408889634f;
    const float INVL2E = 0.6931471805599453f;                // 1/LOG2E
    const float INVN   = 1.0f / (float)NCOL;

    float eps = fmaxf(rmax, 1e-8f) / LOGC;

    // ---- Newton with early exit (eps identical in all threads -> uniform) ----
#pragma unroll 1
    for (int it = 0; it < 20; it++) {
        int pb = (it + 1) & 1;              // iter 0 uses buffer 1 (buffer 0 just used)
        float eps_safe = fmaxf(eps, 1e-8f);
        float binv = __fdividef(1.0f, eps_safe);
        float blog = binv * LOG2E;
        float s1 = 0.f, s2 = 0.f;
#pragma unroll
        for (int j = 0; j < EPT; j++) {
            float a  = r[j] * blog;          // = u * log2(e)
            float e  = ex2(a);
            float ei = ex2(-a);
            s1 += (e - ei);                  // 2*sinh(u)
            s2 = fmaf(e + ei, a, s2);        // 2*cosh(u)*u*LOG2E
        }
        s1 = warpRedSum(s1);
        s2 = warpRedSum(s2);
        if (lane == 0) { pA[pb][wid] = s1; pB[pb][wid] = s2; }
        __syncthreads();
        float S1 = 0.f, S2 = 0.f;
#pragma unroll
        for (int w = 0; w < NWARP; w++) { S1 += pA[pb][w]; S2 += pB[pb][w]; }
        float val  = 0.5f * S1 * INVN - 1.0f;
        float grad = -(0.5f * S2 * INVL2E * INVN) * binv;   // undo LOG2E scaling
        eps = eps - val / (grad - 1e-8f);
        if (fabsf(val) < 3e-5f) break;      // above fp32 noise floor of the mean
    }
    eps = fmaxf(eps, 1e-8f);
    float beta = __fdividef(1.0f, eps + 1e-6f);
    float blg  = beta * LOG2E;

    // ---- q_max analytically: sinh monotone -> max at rmax ----
    float am = rmax * blg;
    float qmax = 0.5f * (ex2(am) - ex2(-am));
    float qinv = __fdividef(1.0f, qmax + 1e-20f);

    // ---- output pass: Lambda update + loss partial ----
    float* outL = out + 1 + (size_t)row * NCOL;
    float ls = 0.f;
#pragma unroll
    for (int k = 0; k < V4PT; k++) {
        int i = tid + k * BDIM;
        float4 lv = lam_sm[i];
        float lm[4] = {lv.x, lv.y, lv.z, lv.w};
        float vo[4];
#pragma unroll
        for (int c = 0; c < 4; c++) {
            float rv = r[4*k + c];
            float a = rv * blg;
            float q = 0.5f * (ex2(a) - ex2(-a));
            float lam_it = fmaf(0.9f, q * qinv, 0.1f);       // PHI*q_norm + (1-PHI)
            float upd = fmaf(0.99f, lm[c], 0.1f * lam_it);   // GAMMA*Lambda + ETA*lam_it
            vo[c] = upd;
            float p = upd * rv;
            ls = fmaf(p, p, ls);
        }
        int base = i * 4;                   // out+1 region is only 4B aligned
        outL[base + 0] = vo[0];
        outL[base + 1] = vo[1];
        outL[base + 2] = vo[2];
        outL[base + 3] = vo[3];
    }
    ls = warpRedSum(ls);
    __syncthreads();                         // protect pB[0] vs last-iter readers
    if (lane == 0) pB[0][wid] = ls;
    __syncthreads();
    if (tid == 0) {
        float s = 0.f;
#pragma unroll
        for (int w = 0; w < NWARP; w++) s += pB[0][w];
        g_rowsum[row] = s;
        __threadfence();
        isLast = (atomicAdd(&g_count, 1u) == BROWS - 1) ? 1u : 0u;
    }
    __syncthreads();

    // ---- last block computes the final loss (deterministic fixed-order sum) ----
    if (isLast) {
        float s = 0.f;
#pragma unroll
        for (int k = 0; k < BROWS / BDIM; k++)
            s += g_rowsum[tid + k * BDIM];
        s = warpRedSum(s);
        if (lane == 0) pA[0][wid] = s;
        __syncthreads();
        if (tid == 0) {
            float t = 0.f;
#pragma unroll
            for (int w = 0; w < NWARP; w++) t += pA[0][w];
            out[0] = t * (1.0f / ((float)BROWS * (float)NCOL));
            g_count = 0;                     // reset for next graph replay
        }
    }
}

extern "C" void kernel_launch(void* const* d_in, const int* in_sizes, int n_in,
                              void* d_out, int out_size)
{
    const float* yp  = (const float*)d_in[0];
    const float* yt  = (const float*)d_in[1];
    const float* Lam = (const float*)d_in[2];
    float* out = (float*)d_out;

    custom_loss_kernel<<<BROWS, BDIM>>>(yp, yt, Lam, out);
}